// round 14
// baseline (speedup 1.0000x reference)
#include <cuda_runtime.h>
#include <cuda_fp16.h>
#include <cstdint>

#define NPHEN 64
#define KSEL  32
#define BB    2048
#define DIN   1024
#define HIDD  2048

// ---------------- scratch (device globals: allowed; no cudaMalloc) ----------
__device__ __align__(16) __half g_w1h[(size_t)NPHEN * HIDD * DIN];  // [p][h][d] fp16
__device__ __align__(16) __half g_xh[(size_t)BB * DIN];             // [b][d]    fp16
__device__ int g_ctr;        // persistent work-item counter
__device__ int g_nuniq;      // number of unique phenotypes selected
__device__ int g_up[KSEL];   // phenotype id per unique item

// ---------------- helpers ---------------------------------------------------
__device__ __forceinline__ uint32_t smem_to_u32(const void* smem_ptr) {
    uint32_t addr;
    asm("{ .reg .u64 tmp; cvta.to.shared.u64 tmp, %1; cvt.u32.u64 %0, tmp; }"
        : "=r"(addr) : "l"(smem_ptr));
    return addr;
}
#define SMEM_SWIZZLE_128B(byte_offset) ((byte_offset) ^ (((byte_offset) >> 3) & 0x70))

// ---------------- subset handling (int32-vs-int64 robust) -------------------
__device__ __forceinline__ int detect64(const int* s) {
    int z = 1;
#pragma unroll
    for (int i = 0; i < 16; i++) z &= (s[2 * i + 1] == 0);
    return z;
}
__device__ __forceinline__ int get_subidx(const int* s, int k, int is64) {
    return is64 ? s[2 * k] : s[k];
}
__device__ __forceinline__ int find_rep(const int* s, int k, int is64) {
    int p = get_subidx(s, k, is64);
    for (int kk = 0; kk < k; ++kk)
        if (get_subidx(s, kk, is64) == p) return kk;
    return k;
}

// ---------------- prep kernel ------------------------------------------------
__global__ void prep_kernel(const float* __restrict__ x,
                            const float* __restrict__ W1,
                            const int* __restrict__ subset,
                            const float* __restrict__ b2,
                            float* __restrict__ out) {
    int tx = threadIdx.x, ty = threadIdx.y;
    if (blockIdx.z == 32) {
        int i2 = (blockIdx.y * 64 + blockIdx.x) * 256 + ty * 32 + tx;
        const float4* src = reinterpret_cast<const float4*>(x);
        __half2* dst = reinterpret_cast<__half2*>(g_xh);
#pragma unroll
        for (int u = 0; u < 2; ++u) {
            int i = 2 * i2 + u;
            float4 v = src[i];
            dst[2 * i]     = __floats2half2_rn(v.x, v.y);
            dst[2 * i + 1] = __floats2half2_rn(v.z, v.w);
        }
        return;
    }
    if (blockIdx.z == 33) {
        int idx = (blockIdx.y * 64 + blockIdx.x) * 256 + ty * 32 + tx;
        int is64 = detect64(subset);
        if (idx < BB * KSEL)
            out[idx] = b2[get_subidx(subset, idx & (KSEL - 1), is64)];
        if (blockIdx.x == 0 && blockIdx.y == 0 && tx == 0 && ty == 0) {
            int nu = 0;                        // scheduler init (one thread)
            for (int k = 0; k < KSEL; ++k)
                if (find_rep(subset, k, is64) == k)
                    g_up[nu++] = get_subidx(subset, k, is64);
            g_nuniq = nu;
            g_ctr = 0;
        }
        return;
    }
    int k = blockIdx.z;
    int is64 = detect64(subset);
    if (find_rep(subset, k, is64) != k) return;  // dedup
    int p = get_subidx(subset, k, is64);
    int h0 = blockIdx.x * 32, d0 = blockIdx.y * 64;
    __shared__ float t[64][33];
#pragma unroll
    for (int i = 0; i < 8; ++i) {
        int dl = ty + i * 8;
        t[dl][tx] = W1[((size_t)p * DIN + d0 + dl) * HIDD + h0 + tx];
    }
    __syncthreads();
#pragma unroll
    for (int i = 0; i < 4; ++i) {
        int hl = ty + i * 8;
        __half2 v = __floats2half2_rn(t[2 * tx][hl], t[2 * tx + 1][hl]);
        *reinterpret_cast<__half2*>(
            &g_w1h[((size_t)p * HIDD + h0 + hl) * DIN + d0 + 2 * tx]) = v;
    }
}

// ---------------- main persistent kernel -------------------------------------
// 296 persistent CTAs (2/SM), 128 thr = 4 warps (2x2), warp tile 64x64.
// Work item = (bt, 2 hid-tiles, unique k); pulled via atomic counter; cp.async
// stream pipelined ACROSS item boundaries (3 stages, one group per iteration).
#define SM_STAGE 32768
#define SM_B1    98304
#define SM_W2    99328
#define SM_ITEM  100352
#define SM_RED   106496
#define SM_TOT   107520
#define NIT      32    // 2 hid-tiles * 16 d-chunks per item

__device__ __forceinline__ void issue_chunk(uint32_t smem_base, int bt, int p,
                                            int h_base, int chunk, int stage,
                                            int tid) {
    const __half* Xh = g_xh + (size_t)bt * 128 * DIN;
    const __half* Wh = g_w1h + (size_t)p * HIDD * DIN;
    int nt = h_base + (chunk >> 4), dc = chunk & 15;
    uint32_t sA = smem_base + stage * SM_STAGE;
    uint32_t sB = sA + 16384;
    int d0 = dc * 64, h0 = nt * 128;
#pragma unroll
    for (int i = 0; i < 8; ++i) {
        int unit = tid + i * 128;
        int r = unit >> 3, q = unit & 7;
        uint32_t off = SMEM_SWIZZLE_128B((uint32_t)(r * 128 + q * 16));
        const __half* ga = Xh + (size_t)r * DIN + d0 + q * 8;
        const __half* gb = Wh + (size_t)(h0 + r) * DIN + d0 + q * 8;
        asm volatile("cp.async.cg.shared.global [%0], [%1], 16;" :: "r"(sA + off), "l"(ga));
        asm volatile("cp.async.cg.shared.global [%0], [%1], 16;" :: "r"(sB + off), "l"(gb));
    }
    asm volatile("cp.async.commit_group;" ::: "memory");
}

__device__ __forceinline__ void fetch_item(int* slot) {   // tid==0 only
    int id = atomicAdd(&g_ctr, 1);
    int total = g_nuniq << 7;    // nuniq * 8 chunks * 16 bt
    if (id >= total) { slot[3] = 0; return; }
    int uk = id >> 7, rem = id & 127;
    slot[0] = rem & 15;          // bt   (fastest: 16 CTAs share B chunk in L2)
    slot[1] = g_up[uk];          // phenotype
    slot[2] = (rem >> 4) * 2;    // h_base in 128-tiles
    slot[3] = 1;
}

__global__ void __launch_bounds__(128, 2)
fused_main_kernel(const int* __restrict__ subset,
                  const float* __restrict__ b1,
                  const float* __restrict__ W2,
                  float* __restrict__ out) {
    extern __shared__ char smem[];
    const uint32_t smem_base = smem_to_u32(smem);
    int tid = threadIdx.x, wid = tid >> 5, lid = tid & 31;
    int wm = wid >> 1, wn = wid & 1;       // 2 x 2 warp grid, 64x64 tiles
    int m0w = wm * 64, n0w = wn * 64;

    int is64 = detect64(subset);
    float* b1s = reinterpret_cast<float*>(smem + SM_B1);   // 256 floats
    float* w2s = reinterpret_cast<float*>(smem + SM_W2);   // 256 floats
    int* slot0 = reinterpret_cast<int*>(smem + SM_ITEM);
    int* slot1 = reinterpret_cast<int*>(smem + SM_ITEM + 16);

    float c[4][8][4];
#pragma unroll
    for (int mf = 0; mf < 4; ++mf)
#pragma unroll
        for (int nf = 0; nf < 8; ++nf)
#pragma unroll
            for (int j = 0; j < 4; ++j) c[mf][nf][j] = 0.0f;
    float accv[8] = {0.f, 0.f, 0.f, 0.f, 0.f, 0.f, 0.f, 0.f};

    uint32_t a[2][16], b[2][16];
    auto lda = [&](int buf, uint32_t sA, int s) {
        int kb = s * 32;
#pragma unroll
        for (int mf = 0; mf < 4; ++mf) {
            int row = m0w + mf * 16 + (lid & 15);
            int byt = kb + (lid >> 4) * 16;
            uint32_t addr = sA + SMEM_SWIZZLE_128B((uint32_t)(row * 128 + byt));
            asm volatile("ldmatrix.sync.aligned.m8n8.x4.shared.b16 {%0,%1,%2,%3}, [%4];"
                         : "=r"(a[buf][mf * 4]), "=r"(a[buf][mf * 4 + 1]),
                           "=r"(a[buf][mf * 4 + 2]), "=r"(a[buf][mf * 4 + 3])
                         : "r"(addr));
        }
    };
    auto ldb = [&](int buf, uint32_t sB, int s) {
        int kb = s * 32;
#pragma unroll
        for (int nq = 0; nq < 4; ++nq) {
            int row = n0w + nq * 16 + ((lid >> 4) * 8) + (lid & 7);
            int byt = kb + ((lid >> 3) & 1) * 16;
            uint32_t addr = sB + SMEM_SWIZZLE_128B((uint32_t)(row * 128 + byt));
            asm volatile("ldmatrix.sync.aligned.m8n8.x4.shared.b16 {%0,%1,%2,%3}, [%4];"
                         : "=r"(b[buf][nq * 4]), "=r"(b[buf][nq * 4 + 1]),
                           "=r"(b[buf][nq * 4 + 2]), "=r"(b[buf][nq * 4 + 3])
                         : "r"(addr));
        }
    };
    auto domma = [&](int buf) {
#pragma unroll
        for (int mf = 0; mf < 4; ++mf)
#pragma unroll
            for (int nf = 0; nf < 8; ++nf) {
                int bi = (nf >> 1) * 4 + (nf & 1) * 2;
                asm volatile(
                    "mma.sync.aligned.m16n8k16.row.col.f32.f16.f16.f32 "
                    "{%0,%1,%2,%3},{%4,%5,%6,%7},{%8,%9},{%0,%1,%2,%3};"
                    : "+f"(c[mf][nf][0]), "+f"(c[mf][nf][1]),
                      "+f"(c[mf][nf][2]), "+f"(c[mf][nf][3])
                    : "r"(a[buf][mf * 4]), "r"(a[buf][mf * 4 + 1]),
                      "r"(a[buf][mf * 4 + 2]), "r"(a[buf][mf * 4 + 3]),
                      "r"(b[buf][bi]), "r"(b[buf][bi + 1]));
            }
    };
    auto loadbias = [&](int p, int h_base) {
        const float2* b1g = reinterpret_cast<const float2*>(b1 + p * HIDD + h_base * 128);
        const float2* w2g = reinterpret_cast<const float2*>(W2 + p * HIDD + h_base * 128);
        reinterpret_cast<float2*>(b1s)[tid] = b1g[tid];
        reinterpret_cast<float2*>(w2s)[tid] = w2g[tid];
    };

    // ---- initial: fetch two items ----
    if (tid == 0) { fetch_item(slot0); fetch_item(slot1); }
    __syncthreads();
    int cbt = slot0[0], cp = slot0[1], chb = slot0[2], cval = slot0[3];
    int nbt = slot1[0], np = slot1[1], nhb = slot1[2], nval = slot1[3];
    if (!cval) return;

    int is_s = 0, cs = 0;   // issue / compute stage counters (mod 3)
    issue_chunk(smem_base, cbt, cp, chb, 0, is_s, tid); is_s = 1;
    issue_chunk(smem_base, cbt, cp, chb, 1, is_s, tid); is_s = 2;
    loadbias(cp, chb);
    asm volatile("cp.async.wait_group 1;" ::: "memory");
    __syncthreads();

    while (true) {
        for (int it = 0; it < NIT; ++it) {
            int nc = it + 2;
            if (nc < NIT)      issue_chunk(smem_base, cbt, cp, chb, nc, is_s, tid);
            else if (nval)     issue_chunk(smem_base, nbt, np, nhb, nc - NIT, is_s, tid);
            else               asm volatile("cp.async.commit_group;" ::: "memory");
            is_s = (is_s + 1) % 3;

            uint32_t sA = smem_base + cs * SM_STAGE;
            uint32_t sB = sA + 16384;
            cs = (cs + 1) % 3;

            lda(0, sA, 0); ldb(0, sB, 0);
#pragma unroll
            for (int s = 0; s < 4; ++s) {
                if (s < 3) { lda((s + 1) & 1, sA, s + 1); ldb((s + 1) & 1, sB, s + 1); }
                domma(s & 1);
            }

            if ((it & 15) == 15) {
                int nt_off = (it >> 4) * 128;
                const float2* b1v = reinterpret_cast<const float2*>(b1s);
                const float2* w2v = reinterpret_cast<const float2*>(w2s);
#pragma unroll
                for (int mf = 0; mf < 4; ++mf)
#pragma unroll
                    for (int nf = 0; nf < 8; ++nf) {
                        int col2 = (nt_off + n0w + nf * 8 + 2 * (lid & 3)) >> 1;
                        float2 bb = b1v[col2];
                        float2 ww = w2v[col2];
                        float v0 = c[mf][nf][0] + bb.x;
                        float v1 = c[mf][nf][1] + bb.y;
                        float v2 = c[mf][nf][2] + bb.x;
                        float v3 = c[mf][nf][3] + bb.y;
                        if (v0 > 0.f) accv[mf * 2]     = fmaf(v0, ww.x, accv[mf * 2]);
                        if (v1 > 0.f) accv[mf * 2]     = fmaf(v1, ww.y, accv[mf * 2]);
                        if (v2 > 0.f) accv[mf * 2 + 1] = fmaf(v2, ww.x, accv[mf * 2 + 1]);
                        if (v3 > 0.f) accv[mf * 2 + 1] = fmaf(v3, ww.y, accv[mf * 2 + 1]);
                        c[mf][nf][0] = c[mf][nf][1] = c[mf][nf][2] = c[mf][nf][3] = 0.0f;
                    }
            }

            asm volatile("cp.async.wait_group 1;" ::: "memory");
            __syncthreads();
        }

        // ---- reduction + atomic accumulate for current item ----
        float* red = reinterpret_cast<float*>(smem + SM_RED);  // [2][128]
#pragma unroll
        for (int j = 0; j < 8; ++j) {
            accv[j] += __shfl_xor_sync(0xffffffffu, accv[j], 1);
            accv[j] += __shfl_xor_sync(0xffffffffu, accv[j], 2);
        }
        if ((lid & 3) == 0) {
            int g = lid >> 2;
#pragma unroll
            for (int mf = 0; mf < 4; ++mf) {
                red[wn * 128 + m0w + mf * 16 + g]     = accv[mf * 2];
                red[wn * 128 + m0w + mf * 16 + g + 8] = accv[mf * 2 + 1];
            }
        }
        __syncthreads();
        {
            int bidx = cbt * 128 + tid;
            float v = red[tid] + red[128 + tid];
#pragma unroll
            for (int kk = 0; kk < KSEL; ++kk)
                if (get_subidx(subset, kk, is64) == cp)
                    atomicAdd(&out[(size_t)bidx * KSEL + kk], v);
        }
#pragma unroll
        for (int j = 0; j < 8; ++j) accv[j] = 0.0f;

        if (!nval) break;
        cbt = nbt; cp = np; chb = nhb; cval = nval;
        loadbias(cp, chb);
        if (tid == 0) fetch_item(slot1);
        __syncthreads();
        nbt = slot1[0]; np = slot1[1]; nhb = slot1[2]; nval = slot1[3];
    }
}

// ---------------- launch ----------------------------------------------------
extern "C" void kernel_launch(void* const* d_in, const int* in_sizes, int n_in,
                              void* d_out, int out_size) {
    const float* x      = (const float*)d_in[0];
    const int*   subset = (const int*)d_in[1];
    const float* W1     = (const float*)d_in[2];
    const float* b1     = (const float*)d_in[3];
    const float* W2     = (const float*)d_in[4];
    const float* b2     = (const float*)d_in[5];
    float* out = (float*)d_out;

    cudaFuncSetAttribute(fused_main_kernel,
                         cudaFuncAttributeMaxDynamicSharedMemorySize, SM_TOT);

    prep_kernel<<<dim3(64, 16, 34), dim3(32, 8)>>>(x, W1, subset, b2, out);
    fused_main_kernel<<<296, 128, SM_TOT>>>(subset, b1, W2, out);
}

// round 15
// speedup vs baseline: 1.0841x; 1.0841x over previous
#include <cuda_runtime.h>
#include <cuda_fp16.h>
#include <cstdint>

#define NPHEN 64
#define KSEL  32
#define BB    2048
#define DIN   1024
#define HIDD  2048

// ---------------- scratch (device globals: allowed; no cudaMalloc) ----------
__device__ __align__(16) __half g_w1h[(size_t)NPHEN * HIDD * DIN];  // [p][h][d] fp16
__device__ __align__(16) __half g_xh[(size_t)BB * DIN];             // [b][d]    fp16

// ---------------- helpers ---------------------------------------------------
__device__ __forceinline__ uint32_t smem_to_u32(const void* smem_ptr) {
    uint32_t addr;
    asm("{ .reg .u64 tmp; cvta.to.shared.u64 tmp, %1; cvt.u32.u64 %0, tmp; }"
        : "=r"(addr) : "l"(smem_ptr));
    return addr;
}
#define SMEM_SWIZZLE_128B(byte_offset) ((byte_offset) ^ (((byte_offset) >> 3) & 0x70))

// ---------------- subset handling (int32-vs-int64 robust) -------------------
__device__ __forceinline__ int detect64(const int* s) {
    int z = 1;
#pragma unroll
    for (int i = 0; i < 16; i++) z &= (s[2 * i + 1] == 0);
    return z;
}
__device__ __forceinline__ int get_subidx(const int* s, int k, int is64) {
    return is64 ? s[2 * k] : s[k];
}
__device__ __forceinline__ int find_rep(const int* s, int k, int is64) {
    int p = get_subidx(s, k, is64);
    for (int kk = 0; kk < k; ++kk)
        if (get_subidx(s, kk, is64) == p) return kk;
    return k;
}

// ---------------- prep kernel ------------------------------------------------
// grid (32, 16, 34), block (32, 8).
//   z in [0,32): transpose+convert W1 for k=z (deduped); tile 64(h) x 64(d)
//   z == 32:     x fp32 -> fp16  (512 blocks x 4096 floats)
//   z == 33:     out init = b2[p_k]
__global__ void prep_kernel(const float* __restrict__ x,
                            const float* __restrict__ W1,
                            const int* __restrict__ subset,
                            const float* __restrict__ b2,
                            float* __restrict__ out) {
    int tx = threadIdx.x, ty = threadIdx.y;
    if (blockIdx.z == 32) {
        int ib = (blockIdx.y * 32 + blockIdx.x) * 1024;   // float4 base
        const float4* src = reinterpret_cast<const float4*>(x);
        __half2* dst = reinterpret_cast<__half2*>(g_xh);
#pragma unroll
        for (int u = 0; u < 4; ++u) {
            int i = ib + u * 256 + ty * 32 + tx;
            float4 v = src[i];
            dst[2 * i]     = __floats2half2_rn(v.x, v.y);
            dst[2 * i + 1] = __floats2half2_rn(v.z, v.w);
        }
        return;
    }
    if (blockIdx.z == 33) {
        int idx = (blockIdx.y * 32 + blockIdx.x) * 256 + ty * 32 + tx;
        if (idx < BB * KSEL) {
            int is64 = detect64(subset);
            out[idx] = b2[get_subidx(subset, idx & (KSEL - 1), is64)];
        }
        return;
    }
    int k = blockIdx.z;
    int is64 = detect64(subset);
    if (find_rep(subset, k, is64) != k) return;  // dedup
    int p = get_subidx(subset, k, is64);
    int h0 = blockIdx.x * 64, d0 = blockIdx.y * 64;

    __shared__ float t[64][65];                  // [hl][dl], 2-way max conflicts
    // read: 64 d-rows, each warp-row reads 64 h as float2 (256B contiguous)
#pragma unroll
    for (int i = 0; i < 8; ++i) {
        int dl = ty + i * 8;
        float2 v = *reinterpret_cast<const float2*>(
            &W1[((size_t)p * DIN + d0 + dl) * HIDD + h0 + 2 * tx]);
        t[2 * tx][dl]     = v.x;
        t[2 * tx + 1][dl] = v.y;
    }
    __syncthreads();
    // write: 64 h-rows, 64 d as half2 (128B contiguous per row)
#pragma unroll
    for (int j = 0; j < 8; ++j) {
        int hl = ty + j * 8;
        __half2 v = __floats2half2_rn(t[hl][2 * tx], t[hl][2 * tx + 1]);
        *reinterpret_cast<__half2*>(
            &g_w1h[((size_t)p * HIDD + h0 + hl) * DIN + d0 + 2 * tx]) = v;
    }
}

// ---------------- main fused kernel (R11 config — best measured) -------------
// grid (16, 64): y = k*2+half; CTA does half of HID (8 tiles of 128).
// 128 threads = 4 warps (2x2), warp tile 64x64. BK=64, 3-stage cp.async.
#define SM_STAGE 32768
#define SM_B1    98304
#define SM_W2    102400
#define SM_RED   106496
#define SM_TOT   107520
#define NIT      128   // 8 hid-tiles * 16 d-chunks

__device__ __forceinline__ void issue_chunk(uint32_t smem_base,
                                            const __half* __restrict__ Xh,
                                            const __half* __restrict__ Wh,
                                            int it, int h_base, int tid) {
    int nt = h_base + (it >> 4), dc = it & 15, stage = it % 3;
    uint32_t sA = smem_base + stage * SM_STAGE;
    uint32_t sB = sA + 16384;
    int d0 = dc * 64, h0 = nt * 128;
#pragma unroll
    for (int i = 0; i < 8; ++i) {
        int unit = tid + i * 128;
        int r = unit >> 3, q = unit & 7;
        uint32_t off = SMEM_SWIZZLE_128B((uint32_t)(r * 128 + q * 16));
        const __half* ga = Xh + (size_t)r * DIN + d0 + q * 8;
        const __half* gb = Wh + (size_t)(h0 + r) * DIN + d0 + q * 8;
        asm volatile("cp.async.cg.shared.global [%0], [%1], 16;" :: "r"(sA + off), "l"(ga));
        asm volatile("cp.async.cg.shared.global [%0], [%1], 16;" :: "r"(sB + off), "l"(gb));
    }
    asm volatile("cp.async.commit_group;" ::: "memory");
}

__global__ void __launch_bounds__(128, 2)
fused_main_kernel(const int* __restrict__ subset,
                  const float* __restrict__ b1,
                  const float* __restrict__ W2,
                  float* __restrict__ out) {
    extern __shared__ char smem[];
    const uint32_t smem_base = smem_to_u32(smem);
    int tid = threadIdx.x, wid = tid >> 5, lid = tid & 31;
    int wm = wid >> 1, wn = wid & 1;       // 2 x 2 warp grid, 64x64 tiles
    int m0w = wm * 64, n0w = wn * 64;
    int bt = blockIdx.x;
    int k = blockIdx.y >> 1, half = blockIdx.y & 1;
    int h_base = half * 8;

    int is64 = detect64(subset);
    if (find_rep(subset, k, is64) != k) return;  // dup columns via atomicAdd below
    int p = get_subidx(subset, k, is64);

    const __half* __restrict__ Xh = g_xh + (size_t)bt * 128 * DIN;
    const __half* __restrict__ Wh = g_w1h + (size_t)p * HIDD * DIN;
    float* b1s = reinterpret_cast<float*>(smem + SM_B1);   // 1024 floats
    float* w2s = reinterpret_cast<float*>(smem + SM_W2);   // 1024 floats

    float c[4][8][4];
#pragma unroll
    for (int mf = 0; mf < 4; ++mf)
#pragma unroll
        for (int nf = 0; nf < 8; ++nf)
#pragma unroll
            for (int j = 0; j < 4; ++j) c[mf][nf][j] = 0.0f;
    float accv[8] = {0.f, 0.f, 0.f, 0.f, 0.f, 0.f, 0.f, 0.f};

    uint32_t a[2][16], b[2][16];

    auto lda = [&](int buf, uint32_t sA, int s) {
        int kb = s * 32;
#pragma unroll
        for (int mf = 0; mf < 4; ++mf) {
            int row = m0w + mf * 16 + (lid & 15);
            int byt = kb + (lid >> 4) * 16;
            uint32_t addr = sA + SMEM_SWIZZLE_128B((uint32_t)(row * 128 + byt));
            asm volatile("ldmatrix.sync.aligned.m8n8.x4.shared.b16 {%0,%1,%2,%3}, [%4];"
                         : "=r"(a[buf][mf * 4]), "=r"(a[buf][mf * 4 + 1]),
                           "=r"(a[buf][mf * 4 + 2]), "=r"(a[buf][mf * 4 + 3])
                         : "r"(addr));
        }
    };
    auto ldb = [&](int buf, uint32_t sB, int s) {
        int kb = s * 32;
#pragma unroll
        for (int nq = 0; nq < 4; ++nq) {
            int row = n0w + nq * 16 + ((lid >> 4) * 8) + (lid & 7);
            int byt = kb + ((lid >> 3) & 1) * 16;
            uint32_t addr = sB + SMEM_SWIZZLE_128B((uint32_t)(row * 128 + byt));
            asm volatile("ldmatrix.sync.aligned.m8n8.x4.shared.b16 {%0,%1,%2,%3}, [%4];"
                         : "=r"(b[buf][nq * 4]), "=r"(b[buf][nq * 4 + 1]),
                           "=r"(b[buf][nq * 4 + 2]), "=r"(b[buf][nq * 4 + 3])
                         : "r"(addr));
        }
    };
    auto domma = [&](int buf) {
#pragma unroll
        for (int mf = 0; mf < 4; ++mf)
#pragma unroll
            for (int nf = 0; nf < 8; ++nf) {
                int bi = (nf >> 1) * 4 + (nf & 1) * 2;
                asm volatile(
                    "mma.sync.aligned.m16n8k16.row.col.f32.f16.f16.f32 "
                    "{%0,%1,%2,%3},{%4,%5,%6,%7},{%8,%9},{%0,%1,%2,%3};"
                    : "+f"(c[mf][nf][0]), "+f"(c[mf][nf][1]),
                      "+f"(c[mf][nf][2]), "+f"(c[mf][nf][3])
                    : "r"(a[buf][mf * 4]), "r"(a[buf][mf * 4 + 1]),
                      "r"(a[buf][mf * 4 + 2]), "r"(a[buf][mf * 4 + 3]),
                      "r"(b[buf][bi]), "r"(b[buf][bi + 1]));
            }
    };

    // prologue: 2 chunks in flight + whole-half b1/w2 preload
    issue_chunk(smem_base, Xh, Wh, 0, h_base, tid);
    issue_chunk(smem_base, Xh, Wh, 1, h_base, tid);
#pragma unroll
    for (int i = 0; i < 8; ++i) {
        int idx = tid + i * 128;
        b1s[idx] = b1[p * HIDD + half * 1024 + idx];
        w2s[idx] = W2[p * HIDD + half * 1024 + idx];
    }
    asm volatile("cp.async.wait_group 1;" ::: "memory");   // chunk 0 ready
    __syncthreads();

    for (int it = 0; it < NIT; ++it) {
        if (it + 2 < NIT) issue_chunk(smem_base, Xh, Wh, it + 2, h_base, tid);

        int stage = it % 3;
        uint32_t sA = smem_base + stage * SM_STAGE;
        uint32_t sB = sA + 16384;

        lda(0, sA, 0); ldb(0, sB, 0);
#pragma unroll
        for (int s = 0; s < 4; ++s) {
            if (s < 3) { lda((s + 1) & 1, sA, s + 1); ldb((s + 1) & 1, sB, s + 1); }
            domma(s & 1);
        }

        // ---- fused epilogue at end of each hid-tile ----
        if ((it & 15) == 15) {
            int nt_off = (it >> 4) * 128;
            const float2* b1v = reinterpret_cast<const float2*>(b1s);
            const float2* w2v = reinterpret_cast<const float2*>(w2s);
#pragma unroll
            for (int mf = 0; mf < 4; ++mf)
#pragma unroll
                for (int nf = 0; nf < 8; ++nf) {
                    int col2 = (nt_off + n0w + nf * 8 + 2 * (lid & 3)) >> 1;
                    float2 bb = b1v[col2];
                    float2 ww = w2v[col2];
                    float v0 = c[mf][nf][0] + bb.x;
                    float v1 = c[mf][nf][1] + bb.y;
                    float v2 = c[mf][nf][2] + bb.x;
                    float v3 = c[mf][nf][3] + bb.y;
                    if (v0 > 0.f) accv[mf * 2]     = fmaf(v0, ww.x, accv[mf * 2]);
                    if (v1 > 0.f) accv[mf * 2]     = fmaf(v1, ww.y, accv[mf * 2]);
                    if (v2 > 0.f) accv[mf * 2 + 1] = fmaf(v2, ww.x, accv[mf * 2 + 1]);
                    if (v3 > 0.f) accv[mf * 2 + 1] = fmaf(v3, ww.y, accv[mf * 2 + 1]);
                    c[mf][nf][0] = c[mf][nf][1] = c[mf][nf][2] = c[mf][nf][3] = 0.0f;
                }
        }

        if (it + 2 < NIT)      asm volatile("cp.async.wait_group 1;" ::: "memory");
        else if (it + 1 < NIT) asm volatile("cp.async.wait_group 0;" ::: "memory");
        __syncthreads();
    }

    // ---- final reduction + atomic accumulate into all duplicate columns ----
    float* red = reinterpret_cast<float*>(smem + SM_RED);  // [2 wn][128 rows]
#pragma unroll
    for (int j = 0; j < 8; ++j) {   // reduce over the 4 col-lanes of each row
        accv[j] += __shfl_xor_sync(0xffffffffu, accv[j], 1);
        accv[j] += __shfl_xor_sync(0xffffffffu, accv[j], 2);
    }
    if ((lid & 3) == 0) {
        int g = lid >> 2;            // 0..7
#pragma unroll
        for (int mf = 0; mf < 4; ++mf) {
            red[wn * 128 + m0w + mf * 16 + g]     = accv[mf * 2];
            red[wn * 128 + m0w + mf * 16 + g + 8] = accv[mf * 2 + 1];
        }
    }
    __syncthreads();
    {
        int b = bt * 128 + tid;
        float v = red[tid] + red[128 + tid];
#pragma unroll
        for (int kk = 0; kk < KSEL; ++kk)
            if (get_subidx(subset, kk, is64) == p)
                atomicAdd(&out[(size_t)b * KSEL + kk], v);
    }
}

// ---------------- launch ----------------------------------------------------
extern "C" void kernel_launch(void* const* d_in, const int* in_sizes, int n_in,
                              void* d_out, int out_size) {
    const float* x      = (const float*)d_in[0];
    const int*   subset = (const int*)d_in[1];
    const float* W1     = (const float*)d_in[2];
    const float* b1     = (const float*)d_in[3];
    const float* W2     = (const float*)d_in[4];
    const float* b2     = (const float*)d_in[5];
    float* out = (float*)d_out;

    cudaFuncSetAttribute(fused_main_kernel,
                         cudaFuncAttributeMaxDynamicSharedMemorySize, SM_TOT);

    prep_kernel<<<dim3(32, 16, 34), dim3(32, 8)>>>(x, W1, subset, b2, out);
    fused_main_kernel<<<dim3(16, 64), 128, SM_TOT>>>(subset, b1, W2, out);
}